// round 1
// baseline (speedup 1.0000x reference)
#include <cuda_runtime.h>

#define N_NEUR   512
#define N_IN     21
#define N_IN_P   24      // padded to multiple of 4 for float4 LDS
#define BATCH_N  65536
#define ROWS     8       // batch rows per block-iteration
#define STEPS    20

__global__ void __launch_bounds__(512, 2)
adex_kernel(const float* __restrict__ x,
            const float* __restrict__ alpha,
            const float* __restrict__ beta,
            const float* __restrict__ delta_t,
            const float* __restrict__ w_in,
            const float* __restrict__ v_thresh,
            const float* __restrict__ v_reset,
            float* __restrict__ out)
{
    __shared__ float s_x[ROWS * N_IN_P];

    const int n = threadIdx.x;  // neuron index, 0..511

    // ---- per-neuron parameters, loaded ONCE per (persistent) block ----
    const float al  = alpha[n];
    const float be  = beta[n];
    const float idt = 1.0f / delta_t[n];
    const float vth = v_thresh[n];
    const float vrs = v_reset[n];

    const float L2E = 1.4426950408889634f;   // log2(e)
    const float l2b = log2f(be);             // beta > 0 always (uniform 0.01..0.11)
    const float a   = idt * L2E;             // t = v*a + bb  (exp2 domain)
    const float bb  = l2b - vth * a;
    const float cap = 10.0f * L2E + l2b;     // clamp folded with +log2(beta)
    const float A   = 1.0f - 0.1f * al;      // v' = A*v + C - 0.1*w_exp
    const float g   = -7.0f * al;            // C = 0.1*I - 7*alpha

    float w[N_IN_P];
    #pragma unroll
    for (int j = 0; j < N_IN_P; j++)
        w[j] = (j < N_IN) ? w_in[n * N_IN + j] : 0.0f;

    const int ngroups = BATCH_N / ROWS;
    for (int bg = blockIdx.x; bg < ngroups; bg += gridDim.x) {
        const int b0 = bg * ROWS;

        __syncthreads();  // previous iteration's readers done with s_x
        if (n < ROWS * N_IN_P) {
            int r = n / N_IN_P;
            int j = n - r * N_IN_P;
            s_x[n] = (j < N_IN) ? x[(b0 + r) * N_IN + j] : 0.0f;
        }
        __syncthreads();

        float v[ROWS], C[ROWS];
        #pragma unroll
        for (int r = 0; r < ROWS; r++) {
            float I = 0.0f;
            const float4* sx4 = reinterpret_cast<const float4*>(&s_x[r * N_IN_P]);
            #pragma unroll
            for (int j4 = 0; j4 < N_IN_P / 4; j4++) {
                float4 xx = sx4[j4];   // broadcast LDS.128, conflict-free
                I = fmaf(w[4 * j4 + 0], xx.x, I);
                I = fmaf(w[4 * j4 + 1], xx.y, I);
                I = fmaf(w[4 * j4 + 2], xx.z, I);
                I = fmaf(w[4 * j4 + 3], xx.w, I);
            }
            C[r] = fmaf(0.1f, I, g);
            v[r] = 0.0f;
        }

        // 20 Euler steps; w (adaptation) never feeds back into v -> dropped.
        #pragma unroll
        for (int s = 0; s < STEPS; s++) {
            #pragma unroll
            for (int r = 0; r < ROWS; r++) {
                float t = fminf(fmaf(v[r], a, bb), cap);
                float e;
                asm("ex2.approx.ftz.f32 %0, %1;" : "=f"(e) : "f"(t));
                float vn = fmaf(A, v[r], C[r]);
                vn = fmaf(-0.1f, e, vn);
                v[r] = (vn > vth) ? vrs : vn;   // spike -> reset
            }
        }

        #pragma unroll
        for (int r = 0; r < ROWS; r++)
            out[(b0 + r) * N_NEUR + n] = v[r];  // coalesced STG.32
    }
}

extern "C" void kernel_launch(void* const* d_in, const int* in_sizes, int n_in,
                              void* d_out, int out_size)
{
    const float* x        = (const float*)d_in[0];
    const float* alpha    = (const float*)d_in[1];
    const float* beta     = (const float*)d_in[2];
    const float* delta_t  = (const float*)d_in[3];
    const float* w_in     = (const float*)d_in[4];
    const float* v_thresh = (const float*)d_in[5];
    const float* v_reset  = (const float*)d_in[6];
    float* out = (float*)d_out;

    // Persistent grid: 2 CTAs/SM target on 148-152 SMs.
    adex_kernel<<<304, 512>>>(x, alpha, beta, delta_t, w_in, v_thresh, v_reset, out);
}